// round 5
// baseline (speedup 1.0000x reference)
#include <cuda_runtime.h>
#include <cuda_bf16.h>
#include <math.h>

#define IN_CH 128
#define H 4
#define C 16
#define HC 64
#define MAXN 100000
#define MAXE 1600000
#define NEG_SLOPE 0.2f
#define SCAN_BLK 256

// scratch (device globals — allocation is forbidden)
__device__ __align__(16) float g_xp[MAXN * HC];      // 25.6 MB
__device__ __align__(16) float g_asrc[MAXN * H];
__device__ __align__(16) float g_adst[MAXN * H];
__device__ int  g_cnt[MAXN];
__device__ int  g_rowptr[MAXN + 1];
__device__ int  g_woff[MAXN];
__device__ int  g_bsum[512];
__device__ int  g_boff[512];
__device__ int2 g_sedge[MAXE];                       // (src, orig edge id), dst-sorted

// ---------------------------------------------------------------------------
// K-hist: histogram of dst into g_cnt  +  edge_index -> float copy
// ---------------------------------------------------------------------------
__global__ void k_hist(const int* __restrict__ ei, float* __restrict__ out_ei,
                       int e) {
    int twoE = 2 * e;
    for (int i = blockIdx.x * blockDim.x + threadIdx.x; i < twoE;
         i += gridDim.x * blockDim.x) {
        int v = ei[i];
        if (out_ei) out_ei[i] = (float)v;
        if (i >= e) atomicAdd(&g_cnt[v], 1);
    }
}

// ---------------------------------------------------------------------------
// scan: 3-phase exclusive prefix sum of g_cnt -> g_rowptr, copy to g_woff
// ---------------------------------------------------------------------------
__global__ void k_scan1(int n) {
    __shared__ int s[SCAN_BLK];
    int t = threadIdx.x;
    int i = blockIdx.x * SCAN_BLK + t;
    int v = (i < n) ? g_cnt[i] : 0;
    s[t] = v;
    __syncthreads();
    #pragma unroll
    for (int off = 1; off < SCAN_BLK; off <<= 1) {
        int a = (t >= off) ? s[t - off] : 0;
        __syncthreads();
        s[t] += a;
        __syncthreads();
    }
    if (i < n) g_rowptr[i] = s[t] - v;
    if (t == SCAN_BLK - 1) g_bsum[blockIdx.x] = s[t];
}

__global__ void k_scan2(int nb) {
    __shared__ int s[512];
    int t = threadIdx.x;
    int v = (t < nb) ? g_bsum[t] : 0;
    s[t] = v;
    __syncthreads();
    #pragma unroll
    for (int off = 1; off < 512; off <<= 1) {
        int a = (t >= off) ? s[t - off] : 0;
        __syncthreads();
        s[t] += a;
        __syncthreads();
    }
    g_boff[t] = s[t] - v;
}

__global__ void k_scan3(int n, int e) {
    int i = blockIdx.x * blockDim.x + threadIdx.x;
    if (i == 0) g_rowptr[n] = e;
    if (i >= n) return;
    int r = g_rowptr[i] + g_boff[i >> 8];
    g_rowptr[i] = r;
    g_woff[i] = r;
}

// ---------------------------------------------------------------------------
// K-permute: scatter edges into dst-sorted order
// ---------------------------------------------------------------------------
__global__ void k_permute(const int* __restrict__ ei, int e) {
    int i = blockIdx.x * blockDim.x + threadIdx.x;
    if (i >= e) return;
    int src = ei[i];
    int dst = ei[e + i];
    int r = atomicAdd(&g_woff[dst], 1);
    g_sedge[r] = make_int2(src, i);
}

// ---------------------------------------------------------------------------
// K1: xp = x @ W, fused a_src/a_dst. 128 nodes/block, 4 nodes x 8 cols/thread
// (1.5 B smem per FMA-lane -> smem crossbar no longer binding)
// ---------------------------------------------------------------------------
__global__ __launch_bounds__(256) void k_gemm(
        const float* __restrict__ x, const float* __restrict__ W,
        const float* __restrict__ att_src, const float* __restrict__ att_dst,
        int n) {
    __shared__ float4 sW4[IN_CH * 16];      // 32 KB
    __shared__ float  sx[128 * 129];        // 66 KB
    int tid = threadIdx.x;
    int tx = tid & 7;        // col group: float4 cols 2tx, 2tx+1 (8 cols)
    int ty = tid >> 3;       // node group: nodes 4ty..4ty+3 (32 groups)
    int node0 = blockIdx.x * 128;

    const float4* W4 = (const float4*)W;
    #pragma unroll
    for (int i = 0; i < (IN_CH * 16) / 256; i++)
        sW4[tid + i * 256] = W4[tid + i * 256];

    #pragma unroll
    for (int i = 0; i < (128 * IN_CH) / 256; i++) {
        int idx = tid + i * 256;
        int nn = idx >> 7, k = idx & 127;
        int node = node0 + nn;
        sx[nn * 129 + k] = (node < n) ? x[(size_t)node * IN_CH + k] : 0.f;
    }
    __syncthreads();

    float4 acc[4][2];
    #pragma unroll
    for (int j = 0; j < 4; j++) {
        acc[j][0] = make_float4(0.f, 0.f, 0.f, 0.f);
        acc[j][1] = make_float4(0.f, 0.f, 0.f, 0.f);
    }

    #pragma unroll 4
    for (int k = 0; k < IN_CH; k++) {
        float4 w0 = sW4[k * 16 + 2 * tx];
        float4 w1 = sW4[k * 16 + 2 * tx + 1];
        #pragma unroll
        for (int j = 0; j < 4; j++) {
            float xv = sx[(ty * 4 + j) * 129 + k];
            acc[j][0].x = fmaf(xv, w0.x, acc[j][0].x);
            acc[j][0].y = fmaf(xv, w0.y, acc[j][0].y);
            acc[j][0].z = fmaf(xv, w0.z, acc[j][0].z);
            acc[j][0].w = fmaf(xv, w0.w, acc[j][0].w);
            acc[j][1].x = fmaf(xv, w1.x, acc[j][1].x);
            acc[j][1].y = fmaf(xv, w1.y, acc[j][1].y);
            acc[j][1].z = fmaf(xv, w1.z, acc[j][1].z);
            acc[j][1].w = fmaf(xv, w1.w, acc[j][1].w);
        }
    }

    float4 as0 = ((const float4*)att_src)[2 * tx];
    float4 as1 = ((const float4*)att_src)[2 * tx + 1];
    float4 ad0 = ((const float4*)att_dst)[2 * tx];
    float4 ad1 = ((const float4*)att_dst)[2 * tx + 1];
    int head = tx >> 1;      // my 8 cols live in this head

    #pragma unroll
    for (int j = 0; j < 4; j++) {
        int node = node0 + ty * 4 + j;
        if (node < n) {
            ((float4*)g_xp)[(size_t)node * 16 + 2 * tx]     = acc[j][0];
            ((float4*)g_xp)[(size_t)node * 16 + 2 * tx + 1] = acc[j][1];
        }
        float s = acc[j][0].x * as0.x + acc[j][0].y * as0.y +
                  acc[j][0].z * as0.z + acc[j][0].w * as0.w +
                  acc[j][1].x * as1.x + acc[j][1].y * as1.y +
                  acc[j][1].z * as1.z + acc[j][1].w * as1.w;
        float d = acc[j][0].x * ad0.x + acc[j][0].y * ad0.y +
                  acc[j][0].z * ad0.z + acc[j][0].w * ad0.w +
                  acc[j][1].x * ad1.x + acc[j][1].y * ad1.y +
                  acc[j][1].z * ad1.z + acc[j][1].w * ad1.w;
        // partner thread (tx^1) holds the other half of this head's 16 cols
        s += __shfl_xor_sync(0xffffffffu, s, 1);
        d += __shfl_xor_sync(0xffffffffu, d, 1);
        if ((tx & 1) == 0 && node < n) {
            g_asrc[node * H + head] = s;
            g_adst[node * H + head] = d;
        }
    }
}

// ---------------------------------------------------------------------------
// K-fuse: warp per dst node.
// Pass 1: denom = sum exp(leaky(a_src[src]+a_dst[dst])) (warp reduce)
// Pass 2: recompute ev, alpha = ev*inv; float4 alpha store by owner lane;
//         broadcast alpha via shuffles; acc += xp[src]*alpha; out = acc+bias
// Zero atomics, zero ev round-trip.
// ---------------------------------------------------------------------------
__global__ __launch_bounds__(256) void k_fuse(
        const float* __restrict__ bias, float* __restrict__ out,
        float* __restrict__ out_alpha, int n) {
    int warp = (blockIdx.x * blockDim.x + threadIdx.x) >> 5;
    int lane = threadIdx.x & 31;
    if (warp >= n) return;
    int node = warp;
    int start = g_rowptr[node], end = g_rowptr[node + 1];
    float4 ad = ((const float4*)g_adst)[node];

    // pass 1: denominator
    float4 sum = make_float4(0.f, 0.f, 0.f, 0.f);
    for (int pos = start + lane; pos < end; pos += 32) {
        int src = g_sedge[pos].x;
        float4 as = ((const float4*)g_asrc)[src];
        float4 l;
        l.x = as.x + ad.x; l.x = l.x > 0.f ? l.x : NEG_SLOPE * l.x;
        l.y = as.y + ad.y; l.y = l.y > 0.f ? l.y : NEG_SLOPE * l.y;
        l.z = as.z + ad.z; l.z = l.z > 0.f ? l.z : NEG_SLOPE * l.z;
        l.w = as.w + ad.w; l.w = l.w > 0.f ? l.w : NEG_SLOPE * l.w;
        sum.x += __expf(l.x); sum.y += __expf(l.y);
        sum.z += __expf(l.z); sum.w += __expf(l.w);
    }
    #pragma unroll
    for (int off = 16; off >= 1; off >>= 1) {
        sum.x += __shfl_xor_sync(0xffffffffu, sum.x, off);
        sum.y += __shfl_xor_sync(0xffffffffu, sum.y, off);
        sum.z += __shfl_xor_sync(0xffffffffu, sum.z, off);
        sum.w += __shfl_xor_sync(0xffffffffu, sum.w, off);
    }
    float4 inv;
    inv.x = 1.f / (sum.x + 1e-16f);
    inv.y = 1.f / (sum.y + 1e-16f);
    inv.z = 1.f / (sum.z + 1e-16f);
    inv.w = 1.f / (sum.w + 1e-16f);

    // pass 2: alpha + aggregation
    int h = lane >> 3;                      // head for my 2 cols
    float2 acc = make_float2(0.f, 0.f);

    for (int base = start; base < end; base += 32) {
        int m = end - base; if (m > 32) m = 32;
        int2 se = make_int2(0, 0);
        float4 alpha = make_float4(0.f, 0.f, 0.f, 0.f);
        if (lane < m) {
            se = g_sedge[base + lane];
            float4 as = ((const float4*)g_asrc)[se.x];
            float4 l;
            l.x = as.x + ad.x; l.x = l.x > 0.f ? l.x : NEG_SLOPE * l.x;
            l.y = as.y + ad.y; l.y = l.y > 0.f ? l.y : NEG_SLOPE * l.y;
            l.z = as.z + ad.z; l.z = l.z > 0.f ? l.z : NEG_SLOPE * l.z;
            l.w = as.w + ad.w; l.w = l.w > 0.f ? l.w : NEG_SLOPE * l.w;
            alpha.x = __expf(l.x) * inv.x;
            alpha.y = __expf(l.y) * inv.y;
            alpha.z = __expf(l.z) * inv.z;
            alpha.w = __expf(l.w) * inv.w;
            if (out_alpha)
                ((float4*)out_alpha)[se.y] = alpha;
        }
        for (int j = 0; j < m; j++) {
            int src  = __shfl_sync(0xffffffffu, se.x, j);
            float a0 = __shfl_sync(0xffffffffu, alpha.x, j);
            float a1 = __shfl_sync(0xffffffffu, alpha.y, j);
            float a2 = __shfl_sync(0xffffffffu, alpha.z, j);
            float a3 = __shfl_sync(0xffffffffu, alpha.w, j);
            float av = (h == 0) ? a0 : (h == 1) ? a1 : (h == 2) ? a2 : a3;
            float2 v = *(const float2*)&g_xp[(size_t)src * HC + 2 * lane];
            acc.x = fmaf(v.x, av, acc.x);
            acc.y = fmaf(v.y, av, acc.y);
        }
    }
    float2 b = *(const float2*)&bias[2 * lane];
    float2 o;
    o.x = acc.x + b.x;
    o.y = acc.y + b.y;
    *(float2*)&out[(size_t)node * HC + 2 * lane] = o;
}

extern "C" void kernel_launch(void* const* d_in, const int* in_sizes, int n_in,
                              void* d_out, int out_size) {
    const float* x       = (const float*)d_in[0];
    const float* W       = (const float*)d_in[1];
    const float* att_src = (const float*)d_in[2];
    const float* att_dst = (const float*)d_in[3];
    const float* bias    = (const float*)d_in[4];
    const int*   ei      = (const int*)d_in[5];

    int n = in_sizes[0] / IN_CH;
    int e = in_sizes[5] / 2;

    float* out = (float*)d_out;
    float* out_ei = nullptr;
    float* out_alpha = nullptr;
    if (out_size >= n * HC + 2 * e) out_ei = out + (size_t)n * HC;
    if (out_size >= n * HC + 2 * e + e * H)
        out_alpha = out + (size_t)n * HC + 2 * e;

    void* cnt_ptr = nullptr;
    cudaGetSymbolAddress(&cnt_ptr, g_cnt);
    cudaMemsetAsync(cnt_ptr, 0, n * sizeof(int));

    // GEMM (independent of edge pipeline)
    k_gemm<<<(n + 127) / 128, 256>>>(x, W, att_src, att_dst, n);

    // histogram + edge_index float copy
    {
        int blocks = (2 * e + 255) / 256;
        if (blocks > 8192) blocks = 8192;
        k_hist<<<blocks, 256>>>(ei, out_ei, e);
    }

    // exclusive scan of counts -> rowptr, woff
    int nb = (n + SCAN_BLK - 1) / SCAN_BLK;
    k_scan1<<<nb, SCAN_BLK>>>(n);
    k_scan2<<<1, 512>>>(nb);
    k_scan3<<<(n + 255) / 256, 256>>>(n, e);

    // permute edges into dst-sorted order
    k_permute<<<(e + 255) / 256, 256>>>(ei, e);

    // fused softmax + aggregation (atomic-free)
    k_fuse<<<(n + 7) / 8, 256>>>(bias, out, out_alpha, n);
}

// round 6
// speedup vs baseline: 1.1663x; 1.1663x over previous
#include <cuda_runtime.h>
#include <cuda_bf16.h>
#include <math.h>

#define IN_CH 128
#define H 4
#define C 16
#define HC 64
#define MAXN 100000
#define MAXE 1600000
#define NEG_SLOPE 0.2f
#define SCAN_BLK 256
#define MAXDEG 64

// scratch (device globals — allocation is forbidden)
__device__ __align__(16) float g_xp[MAXN * HC];      // 25.6 MB
__device__ __align__(16) float g_asrc[MAXN * H];
__device__ __align__(16) float g_adst[MAXN * H];
__device__ int  g_cnt[MAXN];
__device__ int  g_rowptr[MAXN + 1];
__device__ int  g_woff[MAXN];
__device__ int  g_bsum[512];
__device__ int  g_boff[512];
__device__ int2 g_sedge[MAXE];                       // (src, orig edge id), dst-sorted

__device__ __forceinline__ float4 leaky_exp4(float4 as, float4 ad) {
    float4 l;
    l.x = as.x + ad.x; l.x = l.x > 0.f ? l.x : NEG_SLOPE * l.x;
    l.y = as.y + ad.y; l.y = l.y > 0.f ? l.y : NEG_SLOPE * l.y;
    l.z = as.z + ad.z; l.z = l.z > 0.f ? l.z : NEG_SLOPE * l.z;
    l.w = as.w + ad.w; l.w = l.w > 0.f ? l.w : NEG_SLOPE * l.w;
    float4 ev;
    ev.x = __expf(l.x); ev.y = __expf(l.y);
    ev.z = __expf(l.z); ev.w = __expf(l.w);
    return ev;
}

// ---------------------------------------------------------------------------
// K-gemm_hist: block-specialized merge.
// even blockIdx -> gemm tile (128 nodes, 4x8 micro-tile/thread)
// odd  blockIdx -> dst histogram + edge_index float copy (grid-stride)
// ---------------------------------------------------------------------------
__global__ __launch_bounds__(256) void k_gemm_hist(
        const float* __restrict__ x, const float* __restrict__ W,
        const float* __restrict__ att_src, const float* __restrict__ att_dst,
        const int* __restrict__ ei, float* __restrict__ out_ei,
        int n, int e) {
    __shared__ float4 sW4[IN_CH * 16];      // 32 KB
    __shared__ float  sx[128 * 129];        // 66 KB
    int tid = threadIdx.x;

    if (blockIdx.x & 1) {
        // ---- hist + edge copy ----
        int nbh = gridDim.x >> 1;
        int stride = nbh * 256;
        int twoE = 2 * e;
        for (int i = (blockIdx.x >> 1) * 256 + tid; i < twoE; i += stride) {
            int v = ei[i];
            if (out_ei) out_ei[i] = (float)v;
            if (i >= e) atomicAdd(&g_cnt[v], 1);
        }
        return;
    }

    // ---- gemm ----
    int tile = blockIdx.x >> 1;
    int tx = tid & 7;        // col group: float4 cols 2tx, 2tx+1 (8 cols)
    int ty = tid >> 3;       // node group: nodes 4ty..4ty+3
    int node0 = tile * 128;

    const float4* W4 = (const float4*)W;
    #pragma unroll
    for (int i = 0; i < (IN_CH * 16) / 256; i++)
        sW4[tid + i * 256] = W4[tid + i * 256];

    #pragma unroll
    for (int i = 0; i < (128 * IN_CH) / 256; i++) {
        int idx = tid + i * 256;
        int nn = idx >> 7, k = idx & 127;
        int node = node0 + nn;
        sx[nn * 129 + k] = (node < n) ? x[(size_t)node * IN_CH + k] : 0.f;
    }
    __syncthreads();

    float4 acc[4][2];
    #pragma unroll
    for (int j = 0; j < 4; j++) {
        acc[j][0] = make_float4(0.f, 0.f, 0.f, 0.f);
        acc[j][1] = make_float4(0.f, 0.f, 0.f, 0.f);
    }

    #pragma unroll 4
    for (int k = 0; k < IN_CH; k++) {
        float4 w0 = sW4[k * 16 + 2 * tx];
        float4 w1 = sW4[k * 16 + 2 * tx + 1];
        #pragma unroll
        for (int j = 0; j < 4; j++) {
            float xv = sx[(ty * 4 + j) * 129 + k];
            acc[j][0].x = fmaf(xv, w0.x, acc[j][0].x);
            acc[j][0].y = fmaf(xv, w0.y, acc[j][0].y);
            acc[j][0].z = fmaf(xv, w0.z, acc[j][0].z);
            acc[j][0].w = fmaf(xv, w0.w, acc[j][0].w);
            acc[j][1].x = fmaf(xv, w1.x, acc[j][1].x);
            acc[j][1].y = fmaf(xv, w1.y, acc[j][1].y);
            acc[j][1].z = fmaf(xv, w1.z, acc[j][1].z);
            acc[j][1].w = fmaf(xv, w1.w, acc[j][1].w);
        }
    }

    float4 as0 = ((const float4*)att_src)[2 * tx];
    float4 as1 = ((const float4*)att_src)[2 * tx + 1];
    float4 ad0 = ((const float4*)att_dst)[2 * tx];
    float4 ad1 = ((const float4*)att_dst)[2 * tx + 1];
    int head = tx >> 1;

    #pragma unroll
    for (int j = 0; j < 4; j++) {
        int node = node0 + ty * 4 + j;
        if (node < n) {
            ((float4*)g_xp)[(size_t)node * 16 + 2 * tx]     = acc[j][0];
            ((float4*)g_xp)[(size_t)node * 16 + 2 * tx + 1] = acc[j][1];
        }
        float s = acc[j][0].x * as0.x + acc[j][0].y * as0.y +
                  acc[j][0].z * as0.z + acc[j][0].w * as0.w +
                  acc[j][1].x * as1.x + acc[j][1].y * as1.y +
                  acc[j][1].z * as1.z + acc[j][1].w * as1.w;
        float d = acc[j][0].x * ad0.x + acc[j][0].y * ad0.y +
                  acc[j][0].z * ad0.z + acc[j][0].w * ad0.w +
                  acc[j][1].x * ad1.x + acc[j][1].y * ad1.y +
                  acc[j][1].z * ad1.z + acc[j][1].w * ad1.w;
        s += __shfl_xor_sync(0xffffffffu, s, 1);
        d += __shfl_xor_sync(0xffffffffu, d, 1);
        if ((tx & 1) == 0 && node < n) {
            g_asrc[node * H + head] = s;
            g_adst[node * H + head] = d;
        }
    }
}

// ---------------------------------------------------------------------------
// scan: 3-phase exclusive prefix sum of g_cnt -> g_rowptr, copy to g_woff
// ---------------------------------------------------------------------------
__global__ void k_scan1(int n) {
    __shared__ int s[SCAN_BLK];
    int t = threadIdx.x;
    int i = blockIdx.x * SCAN_BLK + t;
    int v = (i < n) ? g_cnt[i] : 0;
    s[t] = v;
    __syncthreads();
    #pragma unroll
    for (int off = 1; off < SCAN_BLK; off <<= 1) {
        int a = (t >= off) ? s[t - off] : 0;
        __syncthreads();
        s[t] += a;
        __syncthreads();
    }
    if (i < n) g_rowptr[i] = s[t] - v;
    if (t == SCAN_BLK - 1) g_bsum[blockIdx.x] = s[t];
}

__global__ void k_scan2(int nb) {
    __shared__ int s[512];
    int t = threadIdx.x;
    int v = (t < nb) ? g_bsum[t] : 0;
    s[t] = v;
    __syncthreads();
    #pragma unroll
    for (int off = 1; off < 512; off <<= 1) {
        int a = (t >= off) ? s[t - off] : 0;
        __syncthreads();
        s[t] += a;
        __syncthreads();
    }
    g_boff[t] = s[t] - v;
}

__global__ void k_scan3(int n, int e) {
    int i = blockIdx.x * blockDim.x + threadIdx.x;
    if (i == 0) g_rowptr[n] = e;
    if (i >= n) return;
    int r = g_rowptr[i] + g_boff[i >> 8];
    g_rowptr[i] = r;
    g_woff[i] = r;
}

// ---------------------------------------------------------------------------
// K-permute: scatter edges into dst-sorted order
// ---------------------------------------------------------------------------
__global__ void k_permute(const int* __restrict__ ei, int e) {
    int i = blockIdx.x * blockDim.x + threadIdx.x;
    if (i >= e) return;
    int src = ei[i];
    int dst = ei[e + i];
    int r = atomicAdd(&g_woff[dst], 1);
    g_sedge[r] = make_int2(src, i);
}

// ---------------------------------------------------------------------------
// K-fuse: warp per dst node, shuffle-free via smem staging.
// Pass 1: ev4 = exp(leaky(a_src[src]+a_dst[dst])) cached in smem (64/warp),
//         warp-reduce denom.
// Pass 2: alpha float4 stores by owner lane; j-loop reads src/ev via LDS
//         broadcast; acc += xp[src]*alpha; out = acc + bias. No atomics.
// ---------------------------------------------------------------------------
__global__ __launch_bounds__(256) void k_fuse(
        const float* __restrict__ bias, float* __restrict__ out,
        float* __restrict__ out_alpha, int n) {
    __shared__ float4 s_ev[8][MAXDEG];   // 8 KB
    __shared__ int2   s_se[8][MAXDEG];   // 4 KB
    int w = threadIdx.x >> 5;
    int lane = threadIdx.x & 31;
    int node = blockIdx.x * 8 + w;
    if (node >= n) return;
    int start = g_rowptr[node], end = g_rowptr[node + 1];
    int deg = end - start;
    float4 ad = ((const float4*)g_adst)[node];

    // pass 1: ev cache + denominator
    float4 sum = make_float4(0.f, 0.f, 0.f, 0.f);
    for (int slot = lane; slot < deg; slot += 32) {
        int2 se = g_sedge[start + slot];
        float4 as = ((const float4*)g_asrc)[se.x];
        float4 ev = leaky_exp4(as, ad);
        if (slot < MAXDEG) {
            s_ev[w][slot] = ev;
            s_se[w][slot] = se;
        }
        sum.x += ev.x; sum.y += ev.y; sum.z += ev.z; sum.w += ev.w;
    }
    #pragma unroll
    for (int off = 16; off >= 1; off >>= 1) {
        sum.x += __shfl_xor_sync(0xffffffffu, sum.x, off);
        sum.y += __shfl_xor_sync(0xffffffffu, sum.y, off);
        sum.z += __shfl_xor_sync(0xffffffffu, sum.z, off);
        sum.w += __shfl_xor_sync(0xffffffffu, sum.w, off);
    }
    float4 inv;
    inv.x = 1.f / (sum.x + 1e-16f);
    inv.y = 1.f / (sum.y + 1e-16f);
    inv.z = 1.f / (sum.z + 1e-16f);
    inv.w = 1.f / (sum.w + 1e-16f);
    __syncwarp();

    int h = lane >> 3;
    float invh = (h == 0) ? inv.x : (h == 1) ? inv.y : (h == 2) ? inv.z : inv.w;
    float2 acc = make_float2(0.f, 0.f);

    for (int base = 0; base < deg; base += 32) {
        int m = deg - base; if (m > 32) m = 32;
        int slot = base + lane;
        // overflow slots (deg > MAXDEG): recompute into wrapped region
        if (slot >= MAXDEG && lane < m) {
            int2 se = g_sedge[start + slot];
            float4 as = ((const float4*)g_asrc)[se.x];
            s_ev[w][slot & (MAXDEG - 1)] = leaky_exp4(as, ad);
            s_se[w][slot & (MAXDEG - 1)] = se;
        }
        __syncwarp();
        if (lane < m && out_alpha) {
            int idx = slot & (MAXDEG - 1);
            float4 ev = s_ev[w][idx];
            float4 al;
            al.x = ev.x * inv.x; al.y = ev.y * inv.y;
            al.z = ev.z * inv.z; al.w = ev.w * inv.w;
            ((float4*)out_alpha)[s_se[w][idx].y] = al;
        }
        for (int j = 0; j < m; j++) {
            int idx = (base + j) & (MAXDEG - 1);
            int src = s_se[w][idx].x;                       // LDS broadcast
            float a = ((const float*)&s_ev[w][idx])[h] * invh;
            float2 v = *(const float2*)&g_xp[(size_t)src * HC + 2 * lane];
            acc.x = fmaf(v.x, a, acc.x);
            acc.y = fmaf(v.y, a, acc.y);
        }
        __syncwarp();
    }
    float2 b = *(const float2*)&bias[2 * lane];
    float2 o;
    o.x = acc.x + b.x;
    o.y = acc.y + b.y;
    *(float2*)&out[(size_t)node * HC + 2 * lane] = o;
}

extern "C" void kernel_launch(void* const* d_in, const int* in_sizes, int n_in,
                              void* d_out, int out_size) {
    const float* x       = (const float*)d_in[0];
    const float* W       = (const float*)d_in[1];
    const float* att_src = (const float*)d_in[2];
    const float* att_dst = (const float*)d_in[3];
    const float* bias    = (const float*)d_in[4];
    const int*   ei      = (const int*)d_in[5];

    int n = in_sizes[0] / IN_CH;
    int e = in_sizes[5] / 2;

    float* out = (float*)d_out;
    float* out_ei = nullptr;
    float* out_alpha = nullptr;
    if (out_size >= n * HC + 2 * e) out_ei = out + (size_t)n * HC;
    if (out_size >= n * HC + 2 * e + e * H)
        out_alpha = out + (size_t)n * HC + 2 * e;

    void* cnt_ptr = nullptr;
    cudaGetSymbolAddress(&cnt_ptr, g_cnt);
    cudaMemsetAsync(cnt_ptr, 0, n * sizeof(int));

    // merged gemm + hist (block-specialized, overlapped)
    int gemmBlocks = (n + 127) / 128;
    k_gemm_hist<<<2 * gemmBlocks, 256>>>(x, W, att_src, att_dst, ei, out_ei,
                                         n, e);

    // exclusive scan of counts -> rowptr, woff
    int nb = (n + SCAN_BLK - 1) / SCAN_BLK;
    k_scan1<<<nb, SCAN_BLK>>>(n);
    k_scan2<<<1, 512>>>(nb);
    k_scan3<<<(n + 255) / 256, 256>>>(n, e);

    // permute edges into dst-sorted order
    k_permute<<<(e + 255) / 256, 256>>>(ei, e);

    // fused softmax + aggregation (atomic-free, shuffle-free inner loop)
    k_fuse<<<(n + 7) / 8, 256>>>(bias, out, out_alpha, n);
}

// round 7
// speedup vs baseline: 1.2443x; 1.0669x over previous
#include <cuda_runtime.h>
#include <cuda_bf16.h>
#include <math.h>

#define IN_CH 128
#define H 4
#define C 16
#define HC 64
#define MAXN 100000
#define MAXE 1600000
#define NEG_SLOPE 0.2f
#define SCAN_BLK 256
#define MAXDEG 64

// scratch (device globals — allocation is forbidden)
__device__ __align__(16) float g_xp[MAXN * HC];      // 25.6 MB
__device__ __align__(16) float g_asrc[MAXN * H];
__device__ __align__(16) float g_adst[MAXN * H];
__device__ int  g_cnt[MAXN];
__device__ int  g_rowptr[MAXN + 1];
__device__ int  g_woff[MAXN];
__device__ int  g_bsum[512];
__device__ int  g_boff[512];
__device__ int2 g_sedge[MAXE];                       // (src, orig edge id), dst-sorted

__device__ __forceinline__ float4 leaky_exp4(float4 as, float4 ad) {
    float4 l;
    l.x = as.x + ad.x; l.x = l.x > 0.f ? l.x : NEG_SLOPE * l.x;
    l.y = as.y + ad.y; l.y = l.y > 0.f ? l.y : NEG_SLOPE * l.y;
    l.z = as.z + ad.z; l.z = l.z > 0.f ? l.z : NEG_SLOPE * l.z;
    l.w = as.w + ad.w; l.w = l.w > 0.f ? l.w : NEG_SLOPE * l.w;
    float4 ev;
    ev.x = __expf(l.x); ev.y = __expf(l.y);
    ev.z = __expf(l.z); ev.w = __expf(l.w);
    return ev;
}

// ---------------------------------------------------------------------------
// K-hist: histogram of dst into g_cnt  +  edge_index -> float copy
// ---------------------------------------------------------------------------
__global__ void k_hist(const int* __restrict__ ei, float* __restrict__ out_ei,
                       int e) {
    int twoE = 2 * e;
    for (int i = blockIdx.x * blockDim.x + threadIdx.x; i < twoE;
         i += gridDim.x * blockDim.x) {
        int v = ei[i];
        if (out_ei) out_ei[i] = (float)v;
        if (i >= e) atomicAdd(&g_cnt[v], 1);
    }
}

// ---------------------------------------------------------------------------
// K-gemm: xp = x @ W, fused a_src/a_dst. 128 nodes/block, 4x8 tile/thread
// ---------------------------------------------------------------------------
__global__ __launch_bounds__(256) void k_gemm(
        const float* __restrict__ x, const float* __restrict__ W,
        const float* __restrict__ att_src, const float* __restrict__ att_dst,
        int n) {
    __shared__ float4 sW4[IN_CH * 16];      // 32 KB
    __shared__ float  sx[128 * 129];        // 66 KB
    int tid = threadIdx.x;
    int tx = tid & 7;        // col group: float4 cols 2tx, 2tx+1
    int ty = tid >> 3;       // node group: nodes 4ty..4ty+3
    int node0 = blockIdx.x * 128;

    const float4* W4 = (const float4*)W;
    #pragma unroll
    for (int i = 0; i < (IN_CH * 16) / 256; i++)
        sW4[tid + i * 256] = W4[tid + i * 256];

    #pragma unroll
    for (int i = 0; i < (128 * IN_CH) / 256; i++) {
        int idx = tid + i * 256;
        int nn = idx >> 7, k = idx & 127;
        int node = node0 + nn;
        sx[nn * 129 + k] = (node < n) ? x[(size_t)node * IN_CH + k] : 0.f;
    }
    __syncthreads();

    float4 acc[4][2];
    #pragma unroll
    for (int j = 0; j < 4; j++) {
        acc[j][0] = make_float4(0.f, 0.f, 0.f, 0.f);
        acc[j][1] = make_float4(0.f, 0.f, 0.f, 0.f);
    }

    #pragma unroll 4
    for (int k = 0; k < IN_CH; k++) {
        float4 w0 = sW4[k * 16 + 2 * tx];
        float4 w1 = sW4[k * 16 + 2 * tx + 1];
        #pragma unroll
        for (int j = 0; j < 4; j++) {
            float xv = sx[(ty * 4 + j) * 129 + k];
            acc[j][0].x = fmaf(xv, w0.x, acc[j][0].x);
            acc[j][0].y = fmaf(xv, w0.y, acc[j][0].y);
            acc[j][0].z = fmaf(xv, w0.z, acc[j][0].z);
            acc[j][0].w = fmaf(xv, w0.w, acc[j][0].w);
            acc[j][1].x = fmaf(xv, w1.x, acc[j][1].x);
            acc[j][1].y = fmaf(xv, w1.y, acc[j][1].y);
            acc[j][1].z = fmaf(xv, w1.z, acc[j][1].z);
            acc[j][1].w = fmaf(xv, w1.w, acc[j][1].w);
        }
    }

    float4 as0 = ((const float4*)att_src)[2 * tx];
    float4 as1 = ((const float4*)att_src)[2 * tx + 1];
    float4 ad0 = ((const float4*)att_dst)[2 * tx];
    float4 ad1 = ((const float4*)att_dst)[2 * tx + 1];
    int head = tx >> 1;

    #pragma unroll
    for (int j = 0; j < 4; j++) {
        int node = node0 + ty * 4 + j;
        if (node < n) {
            ((float4*)g_xp)[(size_t)node * 16 + 2 * tx]     = acc[j][0];
            ((float4*)g_xp)[(size_t)node * 16 + 2 * tx + 1] = acc[j][1];
        }
        float s = acc[j][0].x * as0.x + acc[j][0].y * as0.y +
                  acc[j][0].z * as0.z + acc[j][0].w * as0.w +
                  acc[j][1].x * as1.x + acc[j][1].y * as1.y +
                  acc[j][1].z * as1.z + acc[j][1].w * as1.w;
        float d = acc[j][0].x * ad0.x + acc[j][0].y * ad0.y +
                  acc[j][0].z * ad0.z + acc[j][0].w * ad0.w +
                  acc[j][1].x * ad1.x + acc[j][1].y * ad1.y +
                  acc[j][1].z * ad1.z + acc[j][1].w * ad1.w;
        s += __shfl_xor_sync(0xffffffffu, s, 1);
        d += __shfl_xor_sync(0xffffffffu, d, 1);
        if ((tx & 1) == 0 && node < n) {
            g_asrc[node * H + head] = s;
            g_adst[node * H + head] = d;
        }
    }
}

// ---------------------------------------------------------------------------
// scan: 3-phase exclusive prefix sum of g_cnt -> g_rowptr, copy to g_woff
// ---------------------------------------------------------------------------
__global__ void k_scan1(int n) {
    __shared__ int s[SCAN_BLK];
    int t = threadIdx.x;
    int i = blockIdx.x * SCAN_BLK + t;
    int v = (i < n) ? g_cnt[i] : 0;
    s[t] = v;
    __syncthreads();
    #pragma unroll
    for (int off = 1; off < SCAN_BLK; off <<= 1) {
        int a = (t >= off) ? s[t - off] : 0;
        __syncthreads();
        s[t] += a;
        __syncthreads();
    }
    if (i < n) g_rowptr[i] = s[t] - v;
    if (t == SCAN_BLK - 1) g_bsum[blockIdx.x] = s[t];
}

__global__ void k_scan2(int nb) {
    __shared__ int s[512];
    int t = threadIdx.x;
    int v = (t < nb) ? g_bsum[t] : 0;
    s[t] = v;
    __syncthreads();
    #pragma unroll
    for (int off = 1; off < 512; off <<= 1) {
        int a = (t >= off) ? s[t - off] : 0;
        __syncthreads();
        s[t] += a;
        __syncthreads();
    }
    g_boff[t] = s[t] - v;
}

__global__ void k_scan3(int n, int e) {
    int i = blockIdx.x * blockDim.x + threadIdx.x;
    if (i == 0) g_rowptr[n] = e;
    if (i >= n) return;
    int r = g_rowptr[i] + g_boff[i >> 8];
    g_rowptr[i] = r;
    g_woff[i] = r;
}

// ---------------------------------------------------------------------------
// K-permute: scatter edges into dst-sorted order
// ---------------------------------------------------------------------------
__global__ void k_permute(const int* __restrict__ ei, int e) {
    int i = blockIdx.x * blockDim.x + threadIdx.x;
    if (i >= e) return;
    int src = ei[i];
    int dst = ei[e + i];
    int r = atomicAdd(&g_woff[dst], 1);
    g_sedge[r] = make_int2(src, i);
}

// ---------------------------------------------------------------------------
// K-fuse: warp per dst node, shuffle-free via smem staging.
// ---------------------------------------------------------------------------
__global__ __launch_bounds__(256) void k_fuse(
        const float* __restrict__ bias, float* __restrict__ out,
        float* __restrict__ out_alpha, int n) {
    __shared__ float4 s_ev[8][MAXDEG];   // 8 KB
    __shared__ int2   s_se[8][MAXDEG];   // 4 KB
    int w = threadIdx.x >> 5;
    int lane = threadIdx.x & 31;
    int node = blockIdx.x * 8 + w;
    if (node >= n) return;
    int start = g_rowptr[node], end = g_rowptr[node + 1];
    int deg = end - start;
    float4 ad = ((const float4*)g_adst)[node];

    // pass 1: ev cache + denominator
    float4 sum = make_float4(0.f, 0.f, 0.f, 0.f);
    for (int slot = lane; slot < deg; slot += 32) {
        int2 se = g_sedge[start + slot];
        float4 as = ((const float4*)g_asrc)[se.x];
        float4 ev = leaky_exp4(as, ad);
        if (slot < MAXDEG) {
            s_ev[w][slot] = ev;
            s_se[w][slot] = se;
        }
        sum.x += ev.x; sum.y += ev.y; sum.z += ev.z; sum.w += ev.w;
    }
    #pragma unroll
    for (int off = 16; off >= 1; off >>= 1) {
        sum.x += __shfl_xor_sync(0xffffffffu, sum.x, off);
        sum.y += __shfl_xor_sync(0xffffffffu, sum.y, off);
        sum.z += __shfl_xor_sync(0xffffffffu, sum.z, off);
        sum.w += __shfl_xor_sync(0xffffffffu, sum.w, off);
    }
    float4 inv;
    inv.x = 1.f / (sum.x + 1e-16f);
    inv.y = 1.f / (sum.y + 1e-16f);
    inv.z = 1.f / (sum.z + 1e-16f);
    inv.w = 1.f / (sum.w + 1e-16f);
    __syncwarp();

    int h = lane >> 3;
    float invh = (h == 0) ? inv.x : (h == 1) ? inv.y : (h == 2) ? inv.z : inv.w;
    float2 acc = make_float2(0.f, 0.f);

    for (int base = 0; base < deg; base += 32) {
        int m = deg - base; if (m > 32) m = 32;
        int slot = base + lane;
        // overflow slots (deg > MAXDEG): recompute into wrapped region
        if (slot >= MAXDEG && lane < m) {
            int2 se = g_sedge[start + slot];
            float4 as = ((const float4*)g_asrc)[se.x];
            s_ev[w][slot & (MAXDEG - 1)] = leaky_exp4(as, ad);
            s_se[w][slot & (MAXDEG - 1)] = se;
        }
        __syncwarp();
        if (lane < m && out_alpha) {
            int idx = slot & (MAXDEG - 1);
            float4 ev = s_ev[w][idx];
            float4 al;
            al.x = ev.x * inv.x; al.y = ev.y * inv.y;
            al.z = ev.z * inv.z; al.w = ev.w * inv.w;
            ((float4*)out_alpha)[s_se[w][idx].y] = al;
        }
        #pragma unroll 4
        for (int j = 0; j < m; j++) {
            int idx = (base + j) & (MAXDEG - 1);
            int src = s_se[w][idx].x;                       // LDS broadcast
            float a = ((const float*)&s_ev[w][idx])[h] * invh;
            float2 v = *(const float2*)&g_xp[(size_t)src * HC + 2 * lane];
            acc.x = fmaf(v.x, a, acc.x);
            acc.y = fmaf(v.y, a, acc.y);
        }
        __syncwarp();
    }
    float2 b = *(const float2*)&bias[2 * lane];
    float2 o;
    o.x = acc.x + b.x;
    o.y = acc.y + b.y;
    *(float2*)&out[(size_t)node * HC + 2 * lane] = o;
}

// lazily-created side stream + events (resource init only; the launched work
// is identical on every call, so graph capture sees the same graph each time)
static cudaStream_t g_s2 = nullptr;
static cudaEvent_t  g_evFork = nullptr, g_evJoin = nullptr;

extern "C" void kernel_launch(void* const* d_in, const int* in_sizes, int n_in,
                              void* d_out, int out_size) {
    const float* x       = (const float*)d_in[0];
    const float* W       = (const float*)d_in[1];
    const float* att_src = (const float*)d_in[2];
    const float* att_dst = (const float*)d_in[3];
    const float* bias    = (const float*)d_in[4];
    const int*   ei      = (const int*)d_in[5];

    if (!g_s2) {
        cudaStreamCreateWithFlags(&g_s2, cudaStreamNonBlocking);
        cudaEventCreateWithFlags(&g_evFork, cudaEventDisableTiming);
        cudaEventCreateWithFlags(&g_evJoin, cudaEventDisableTiming);
    }

    int n = in_sizes[0] / IN_CH;
    int e = in_sizes[5] / 2;

    float* out = (float*)d_out;
    float* out_ei = nullptr;
    float* out_alpha = nullptr;
    if (out_size >= n * HC + 2 * e) out_ei = out + (size_t)n * HC;
    if (out_size >= n * HC + 2 * e + e * H)
        out_alpha = out + (size_t)n * HC + 2 * e;

    void* cnt_ptr = nullptr;
    cudaGetSymbolAddress(&cnt_ptr, g_cnt);

    // ---- fork: GEMM on side stream (independent of CSR build) ----
    cudaEventRecord(g_evFork, 0);
    cudaStreamWaitEvent(g_s2, g_evFork, 0);
    k_gemm<<<(n + 127) / 128, 256, 0, g_s2>>>(x, W, att_src, att_dst, n);
    cudaEventRecord(g_evJoin, g_s2);

    // ---- main stream: CSR build ----
    cudaMemsetAsync(cnt_ptr, 0, n * sizeof(int));
    {
        int blocks = (2 * e + 255) / 256;
        if (blocks > 4096) blocks = 4096;
        k_hist<<<blocks, 256>>>(ei, out_ei, e);
    }
    int nb = (n + SCAN_BLK - 1) / SCAN_BLK;
    k_scan1<<<nb, SCAN_BLK>>>(n);
    k_scan2<<<1, 512>>>(nb);
    k_scan3<<<(n + 255) / 256, 256>>>(n, e);
    k_permute<<<(e + 255) / 256, 256>>>(ei, e);

    // ---- join: fuse needs both GEMM results and sorted edges ----
    cudaStreamWaitEvent(0, g_evJoin, 0);
    k_fuse<<<(n + 7) / 8, 256>>>(bias, out, out_alpha, n);
}

// round 8
// speedup vs baseline: 1.3139x; 1.0559x over previous
#include <cuda_runtime.h>
#include <cuda_bf16.h>
#include <math.h>

#define IN_CH 128
#define H 4
#define C 16
#define HC 64
#define MAXN 100000
#define MAXE 1600000
#define NEG_SLOPE 0.2f
#define SCAN_BLK 512
#define MAXDEG 64

// scratch (device globals — allocation is forbidden)
__device__ __align__(16) float g_xp[MAXN * HC];      // 25.6 MB
__device__ __align__(16) float g_asrc[MAXN * H];
__device__ __align__(16) float g_adst[MAXN * H];
__device__ int  g_cnt[MAXN];        // zero-initialized; self-restored each call
__device__ int  g_rowptr[MAXN];     // partial (within-block) exclusive prefix
__device__ int  g_woff[MAXN];       // copy of partial prefix, atomically bumped
__device__ int  g_bsum[SCAN_BLK];
__device__ int  g_boff[SCAN_BLK];
__device__ int  g_scancnt;          // block-done counter; self-restored
__device__ int2 g_sedge[MAXE];      // (src, orig edge id), dst-sorted

__device__ __forceinline__ float4 leaky_exp4(float4 as, float4 ad) {
    float4 l;
    l.x = as.x + ad.x; l.x = l.x > 0.f ? l.x : NEG_SLOPE * l.x;
    l.y = as.y + ad.y; l.y = l.y > 0.f ? l.y : NEG_SLOPE * l.y;
    l.z = as.z + ad.z; l.z = l.z > 0.f ? l.z : NEG_SLOPE * l.z;
    l.w = as.w + ad.w; l.w = l.w > 0.f ? l.w : NEG_SLOPE * l.w;
    float4 ev;
    ev.x = __expf(l.x); ev.y = __expf(l.y);
    ev.z = __expf(l.z); ev.w = __expf(l.w);
    return ev;
}

// ---------------------------------------------------------------------------
// K-hist: histogram of dst into g_cnt  +  edge_index -> float copy
// ---------------------------------------------------------------------------
__global__ void k_hist(const int* __restrict__ ei, float* __restrict__ out_ei,
                       int e) {
    int twoE = 2 * e;
    for (int i = blockIdx.x * blockDim.x + threadIdx.x; i < twoE;
         i += gridDim.x * blockDim.x) {
        int v = ei[i];
        if (out_ei) out_ei[i] = (float)v;
        if (i >= e) atomicAdd(&g_cnt[v], 1);
    }
}

// ---------------------------------------------------------------------------
// K-scan: per-block exclusive scan of g_cnt (self-zeroing) -> rowptr/woff
// (partial); last finished block scans the block sums -> g_boff.
// Final rowptr value = partial + g_boff[i >> 9] (consumers add inline).
// ---------------------------------------------------------------------------
__global__ __launch_bounds__(SCAN_BLK) void k_scan(int n) {
    __shared__ int s[SCAN_BLK];
    __shared__ int lastdone;
    int t = threadIdx.x;
    int i = blockIdx.x * SCAN_BLK + t;
    int v = 0;
    if (i < n) {
        v = g_cnt[i];
        g_cnt[i] = 0;               // restore invariant for next call
    }
    s[t] = v;
    __syncthreads();
    #pragma unroll
    for (int off = 1; off < SCAN_BLK; off <<= 1) {
        int a = (t >= off) ? s[t - off] : 0;
        __syncthreads();
        s[t] += a;
        __syncthreads();
    }
    if (i < n) {
        int r = s[t] - v;           // exclusive within block
        g_rowptr[i] = r;
        g_woff[i] = r;
    }
    if (t == SCAN_BLK - 1) g_bsum[blockIdx.x] = s[t];

    // last-done block scans block sums
    __threadfence();
    if (t == 0) {
        int d = atomicAdd(&g_scancnt, 1);
        lastdone = (d == gridDim.x - 1);
    }
    __syncthreads();
    if (!lastdone) return;
    int nb = gridDim.x;
    int bv = (t < nb) ? g_bsum[t] : 0;
    s[t] = bv;
    __syncthreads();
    #pragma unroll
    for (int off = 1; off < SCAN_BLK; off <<= 1) {
        int a = (t >= off) ? s[t - off] : 0;
        __syncthreads();
        s[t] += a;
        __syncthreads();
    }
    g_boff[t] = s[t] - bv;          // exclusive block offsets
    if (t == 0) g_scancnt = 0;      // restore invariant
}

// ---------------------------------------------------------------------------
// K-permute: scatter edges into dst-sorted order (boff added inline)
// ---------------------------------------------------------------------------
__global__ void k_permute(const int* __restrict__ ei, int e) {
    int i = blockIdx.x * blockDim.x + threadIdx.x;
    if (i >= e) return;
    int src = ei[i];
    int dst = ei[e + i];
    int r = atomicAdd(&g_woff[dst], 1) + g_boff[dst >> 9];
    g_sedge[r] = make_int2(src, i);
}

// ---------------------------------------------------------------------------
// K-gemm: xp = x @ W, fused a_src/a_dst. 128 nodes/block, 4x8 tile/thread
// ---------------------------------------------------------------------------
__global__ __launch_bounds__(256) void k_gemm(
        const float* __restrict__ x, const float* __restrict__ W,
        const float* __restrict__ att_src, const float* __restrict__ att_dst,
        int n) {
    __shared__ float4 sW4[IN_CH * 16];      // 32 KB
    __shared__ float  sx[128 * 129];        // 66 KB
    int tid = threadIdx.x;
    int tx = tid & 7;
    int ty = tid >> 3;
    int node0 = blockIdx.x * 128;

    const float4* W4 = (const float4*)W;
    #pragma unroll
    for (int i = 0; i < (IN_CH * 16) / 256; i++)
        sW4[tid + i * 256] = W4[tid + i * 256];

    #pragma unroll
    for (int i = 0; i < (128 * IN_CH) / 256; i++) {
        int idx = tid + i * 256;
        int nn = idx >> 7, k = idx & 127;
        int node = node0 + nn;
        sx[nn * 129 + k] = (node < n) ? x[(size_t)node * IN_CH + k] : 0.f;
    }
    __syncthreads();

    float4 acc[4][2];
    #pragma unroll
    for (int j = 0; j < 4; j++) {
        acc[j][0] = make_float4(0.f, 0.f, 0.f, 0.f);
        acc[j][1] = make_float4(0.f, 0.f, 0.f, 0.f);
    }

    #pragma unroll 4
    for (int k = 0; k < IN_CH; k++) {
        float4 w0 = sW4[k * 16 + 2 * tx];
        float4 w1 = sW4[k * 16 + 2 * tx + 1];
        #pragma unroll
        for (int j = 0; j < 4; j++) {
            float xv = sx[(ty * 4 + j) * 129 + k];
            acc[j][0].x = fmaf(xv, w0.x, acc[j][0].x);
            acc[j][0].y = fmaf(xv, w0.y, acc[j][0].y);
            acc[j][0].z = fmaf(xv, w0.z, acc[j][0].z);
            acc[j][0].w = fmaf(xv, w0.w, acc[j][0].w);
            acc[j][1].x = fmaf(xv, w1.x, acc[j][1].x);
            acc[j][1].y = fmaf(xv, w1.y, acc[j][1].y);
            acc[j][1].z = fmaf(xv, w1.z, acc[j][1].z);
            acc[j][1].w = fmaf(xv, w1.w, acc[j][1].w);
        }
    }

    float4 as0 = ((const float4*)att_src)[2 * tx];
    float4 as1 = ((const float4*)att_src)[2 * tx + 1];
    float4 ad0 = ((const float4*)att_dst)[2 * tx];
    float4 ad1 = ((const float4*)att_dst)[2 * tx + 1];
    int head = tx >> 1;

    #pragma unroll
    for (int j = 0; j < 4; j++) {
        int node = node0 + ty * 4 + j;
        if (node < n) {
            ((float4*)g_xp)[(size_t)node * 16 + 2 * tx]     = acc[j][0];
            ((float4*)g_xp)[(size_t)node * 16 + 2 * tx + 1] = acc[j][1];
        }
        float s = acc[j][0].x * as0.x + acc[j][0].y * as0.y +
                  acc[j][0].z * as0.z + acc[j][0].w * as0.w +
                  acc[j][1].x * as1.x + acc[j][1].y * as1.y +
                  acc[j][1].z * as1.z + acc[j][1].w * as1.w;
        float d = acc[j][0].x * ad0.x + acc[j][0].y * ad0.y +
                  acc[j][0].z * ad0.z + acc[j][0].w * ad0.w +
                  acc[j][1].x * ad1.x + acc[j][1].y * ad1.y +
                  acc[j][1].z * ad1.z + acc[j][1].w * ad1.w;
        s += __shfl_xor_sync(0xffffffffu, s, 1);
        d += __shfl_xor_sync(0xffffffffu, d, 1);
        if ((tx & 1) == 0 && node < n) {
            g_asrc[node * H + head] = s;
            g_adst[node * H + head] = d;
        }
    }
}

// ---------------------------------------------------------------------------
// K-fuse: warp per dst node, smem-staged, 2 edges/iter via half-warps.
// Each lane owns 4 cols (float4); halves combined by shuffle at the end.
// ---------------------------------------------------------------------------
__global__ __launch_bounds__(256) void k_fuse(
        const float* __restrict__ bias, float* __restrict__ out,
        float* __restrict__ out_alpha, int n, int e) {
    __shared__ float4 s_ev[8][MAXDEG];   // 8 KB
    __shared__ int2   s_se[8][MAXDEG];   // 4 KB
    int w = threadIdx.x >> 5;
    int lane = threadIdx.x & 31;
    int node = blockIdx.x * 8 + w;
    if (node >= n) return;
    int start = g_rowptr[node] + g_boff[node >> 9];
    int end = (node == n - 1) ? e
            : g_rowptr[node + 1] + g_boff[(node + 1) >> 9];
    int deg = end - start;
    float4 ad = ((const float4*)g_adst)[node];

    // pass 1: ev cache + denominator
    float4 sum = make_float4(0.f, 0.f, 0.f, 0.f);
    for (int slot = lane; slot < deg; slot += 32) {
        int2 se = g_sedge[start + slot];
        float4 as = ((const float4*)g_asrc)[se.x];
        float4 ev = leaky_exp4(as, ad);
        if (slot < MAXDEG) {
            s_ev[w][slot] = ev;
            s_se[w][slot] = se;
        }
        sum.x += ev.x; sum.y += ev.y; sum.z += ev.z; sum.w += ev.w;
    }
    #pragma unroll
    for (int off = 16; off >= 1; off >>= 1) {
        sum.x += __shfl_xor_sync(0xffffffffu, sum.x, off);
        sum.y += __shfl_xor_sync(0xffffffffu, sum.y, off);
        sum.z += __shfl_xor_sync(0xffffffffu, sum.z, off);
        sum.w += __shfl_xor_sync(0xffffffffu, sum.w, off);
    }
    float4 inv;
    inv.x = 1.f / (sum.x + 1e-16f);
    inv.y = 1.f / (sum.y + 1e-16f);
    inv.z = 1.f / (sum.z + 1e-16f);
    inv.w = 1.f / (sum.w + 1e-16f);
    __syncwarp();

    int half = lane >> 4;        // 0 or 1: which edge of the pair
    int hl   = lane & 15;        // my float4 column group (4 cols)
    int h    = hl >> 2;          // head
    float invh = (h == 0) ? inv.x : (h == 1) ? inv.y :
                 (h == 2) ? inv.z : inv.w;
    float4 acc = make_float4(0.f, 0.f, 0.f, 0.f);

    for (int base = 0; base < deg; base += 32) {
        int m = deg - base; if (m > 32) m = 32;
        int slot = base + lane;
        // overflow slots (deg > MAXDEG): recompute into wrapped region
        if (slot >= MAXDEG && lane < m) {
            int2 se = g_sedge[start + slot];
            float4 as = ((const float4*)g_asrc)[se.x];
            s_ev[w][slot & (MAXDEG - 1)] = leaky_exp4(as, ad);
            s_se[w][slot & (MAXDEG - 1)] = se;
        }
        __syncwarp();
        if (lane < m && out_alpha) {
            int idx = slot & (MAXDEG - 1);
            float4 ev = s_ev[w][idx];
            float4 al;
            al.x = ev.x * inv.x; al.y = ev.y * inv.y;
            al.z = ev.z * inv.z; al.w = ev.w * inv.w;
            ((float4*)out_alpha)[s_se[w][idx].y] = al;
        }
        int pairs = (m + 1) >> 1;
        #pragma unroll 4
        for (int j = 0; j < pairs; j++) {
            int eo = 2 * j + half;
            int idx = (base + eo) & (MAXDEG - 1);
            int src = s_se[w][idx].x;                       // LDS broadcast
            float a = ((const float*)&s_ev[w][idx])[h] * invh;
            if (eo < m) {
                float4 v = ((const float4*)&g_xp[(size_t)src * HC])[hl];
                acc.x = fmaf(v.x, a, acc.x);
                acc.y = fmaf(v.y, a, acc.y);
                acc.z = fmaf(v.z, a, acc.z);
                acc.w = fmaf(v.w, a, acc.w);
            }
        }
        __syncwarp();
    }
    // combine the two halves
    acc.x += __shfl_xor_sync(0xffffffffu, acc.x, 16);
    acc.y += __shfl_xor_sync(0xffffffffu, acc.y, 16);
    acc.z += __shfl_xor_sync(0xffffffffu, acc.z, 16);
    acc.w += __shfl_xor_sync(0xffffffffu, acc.w, 16);
    if (half == 0) {
        float4 b = ((const float4*)bias)[hl];
        float4 o;
        o.x = acc.x + b.x; o.y = acc.y + b.y;
        o.z = acc.z + b.z; o.w = acc.w + b.w;
        ((float4*)&out[(size_t)node * HC])[hl] = o;
    }
}

// lazily-created side stream + events (resource init only; the launched work
// is identical on every call, so graph capture sees the same graph each time)
static cudaStream_t g_s2 = nullptr;
static cudaEvent_t  g_evFork = nullptr, g_evJoin = nullptr;

extern "C" void kernel_launch(void* const* d_in, const int* in_sizes, int n_in,
                              void* d_out, int out_size) {
    const float* x       = (const float*)d_in[0];
    const float* W       = (const float*)d_in[1];
    const float* att_src = (const float*)d_in[2];
    const float* att_dst = (const float*)d_in[3];
    const float* bias    = (const float*)d_in[4];
    const int*   ei      = (const int*)d_in[5];

    if (!g_s2) {
        cudaStreamCreateWithFlags(&g_s2, cudaStreamNonBlocking);
        cudaEventCreateWithFlags(&g_evFork, cudaEventDisableTiming);
        cudaEventCreateWithFlags(&g_evJoin, cudaEventDisableTiming);
    }

    int n = in_sizes[0] / IN_CH;
    int e = in_sizes[5] / 2;

    float* out = (float*)d_out;
    float* out_ei = nullptr;
    float* out_alpha = nullptr;
    if (out_size >= n * HC + 2 * e) out_ei = out + (size_t)n * HC;
    if (out_size >= n * HC + 2 * e + e * H)
        out_alpha = out + (size_t)n * HC + 2 * e;

    // ---- fork: GEMM on side stream (independent of CSR build) ----
    cudaEventRecord(g_evFork, 0);
    cudaStreamWaitEvent(g_s2, g_evFork, 0);
    k_gemm<<<(n + 127) / 128, 256, 0, g_s2>>>(x, W, att_src, att_dst, n);
    cudaEventRecord(g_evJoin, g_s2);

    // ---- main stream: CSR build (3 kernels) ----
    {
        int blocks = (2 * e + 255) / 256;
        if (blocks > 4096) blocks = 4096;
        k_hist<<<blocks, 256>>>(ei, out_ei, e);
    }
    int nb = (n + SCAN_BLK - 1) / SCAN_BLK;   // 196 <= SCAN_BLK
    k_scan<<<nb, SCAN_BLK>>>(n);
    k_permute<<<(e + 255) / 256, 256>>>(ei, e);

    // ---- join: fuse needs both GEMM results and sorted edges ----
    cudaStreamWaitEvent(0, g_evJoin, 0);
    k_fuse<<<(n + 7) / 8, 256>>>(bias, out, out_alpha, n, e);
}